// round 15
// baseline (speedup 1.0000x reference)
#include <cuda_runtime.h>
#include <cuda_fp16.h>
#include <math.h>
#include <stddef.h>
#include <stdint.h>

#define CDIM 768
#define NHEAD 12
#define HDIM 64
#define BBATCH 4
#define TT 16
#define KPATCH 196
#define LSEQ 3137           // 1 + K*T
#define BKR 784             // B*K
#define MT 12544            // BKR*TT
#define SSP 64              // B*T
#define LSP 197             // 1 + K
#define MSP 12608           // SSP*LSP
#define MOUT 12548          // B*LSEQ
#define HID 3072
#define KT 3136             // KPATCH*TT
#define ATT_SCALE 0.125f    // (64)^-0.5

typedef __half h16;

// ------------------------- device scratch (static, allocation-free) ---------
__device__ float g_x16   [(size_t)MT   * CDIM];
__device__ float g_x8    [(size_t)BKR * 8 * CDIM];
__device__ float g_x4    [(size_t)BKR * 4 * CDIM];
__device__ float g_xtfull[(size_t)MT   * CDIM];
__device__ float g_ressp [(size_t)MSP  * CDIM];
__device__ float g_clssp [(size_t)SSP  * CDIM];
__device__ float g_clsout[(size_t)BBATCH * CDIM];
__device__ float g_xcat  [(size_t)MOUT * CDIM];

// fp16 activation planes
#define PA_ELEMS ((size_t)MSP * CDIM)
__device__ h16 g_pah  [PA_ELEMS];
__device__ h16 g_pbh  [PA_ELEMS];
__device__ h16 g_pbh8 [(size_t)BKR * 8 * CDIM];
__device__ h16 g_pbh4 [(size_t)BKR * 4 * CDIM];
__device__ h16 g_pch  [(size_t)MT * CDIM];
__device__ h16 g_h1h  [(size_t)MOUT * HID];
__device__ h16 g_qkvh [(size_t)MSP * 3 * CDIM];     // chain16 + spatial reuse
__device__ h16 g_qkvh8[(size_t)BKR * 8 * 3 * CDIM];
__device__ h16 g_qkvh4[(size_t)BKR * 4 * 3 * CDIM];

// weight plane (fp16), [K,N] row-major
#define WPOOL 14745600
__device__ h16 g_wh[(size_t)WPOOL];
#define OFF_QKV_S   0u
#define OFF_QKV4    1769472u
#define OFF_QKV8    3538944u
#define OFF_QKV16   5308416u
#define OFF_P_S     7077888u
#define OFF_P4      7667712u
#define OFF_P8      8257536u
#define OFF_P16     8847360u
#define OFF_TFC     9437184u
#define OFF_FC1    10027008u
#define OFF_FC2    12386304u

// ------------------------- weight conversion (single launch) ----------------
struct WPack {
    const float* src[11];
    unsigned dstoff[11];
    unsigned n4[11];
};

__global__ void convW_all_kernel(WPack p, h16* __restrict__ wh) {
    int s = blockIdx.y;
    unsigned i = blockIdx.x * 256u + threadIdx.x;
    if (i >= p.n4[s]) return;
    float4 v = ((const float4*)p.src[s])[i];
    unsigned short h0 = __half_as_ushort(__float2half_rn(v.x));
    unsigned short h1 = __half_as_ushort(__float2half_rn(v.y));
    unsigned short h2 = __half_as_ushort(__float2half_rn(v.z));
    unsigned short h3 = __half_as_ushort(__float2half_rn(v.w));
    ((uint2*)(wh + p.dstoff[s]))[i] =
        make_uint2((uint32_t)h0 | ((uint32_t)h1 << 16),
                   (uint32_t)h2 | ((uint32_t)h3 << 16));
}

// ------------------------- MMA primitives ------------------------------------
#define LDSM4(R, addr) \
    asm volatile("ldmatrix.sync.aligned.m8n8.x4.shared.b16 {%0,%1,%2,%3}, [%4];" \
                 : "=r"(R[0]), "=r"(R[1]), "=r"(R[2]), "=r"(R[3]) : "r"(addr))
#define LDSM4T(R, addr) \
    asm volatile("ldmatrix.sync.aligned.m8n8.x4.trans.shared.b16 {%0,%1,%2,%3}, [%4];" \
                 : "=r"(R[0]), "=r"(R[1]), "=r"(R[2]), "=r"(R[3]) : "r"(addr))
#define MMA_F16(d, a, b0, b1) \
    asm volatile("mma.sync.aligned.m16n8k16.row.col.f32.f16.f16.f32 " \
                 "{%0,%1,%2,%3}, {%4,%5,%6,%7}, {%8,%9}, {%0,%1,%2,%3};" \
                 : "+f"(d[0]), "+f"(d[1]), "+f"(d[2]), "+f"(d[3]) \
                 : "r"(a[0]), "r"(a[1]), "r"(a[2]), "r"(a[3]), "r"(b0), "r"(b1))

__device__ __forceinline__ int swizB(int k, int n) {   // B tile row 256B
    int b = (k << 8) | (n << 1);
    return b ^ ((k & 7) << 4);
}
__device__ __forceinline__ int swiz128(int boff) {     // 128B rows
    return boff ^ ((boff >> 3) & 0x70);
}

__device__ __forceinline__ void cp16(uint32_t dst, const void* src, int sz) {
    asm volatile("cp.async.cg.shared.global [%0], [%1], 16, %2;"
                 :: "r"(dst), "l"(src), "r"(sz));
}

// ======================= tensor-core GEMM (fp16, BK=64) ======================
// rmode: 0 none, 1 resid[r*N+c], 2 resid = x with row map r -> bb*LSEQ+1+off
// amap : 0 identity, else Ts — A row m reads pah row (m/Ts)*TT + (TT-Ts) + m%Ts
// per-stage: A @0 (16KB, 128x64 rows of 128B) | B @16384 (16KB, 64x128)
#define GEMM_STAGES 3
#define STAGE_BYTES 32768u
#define GEMM_SMEM (GEMM_STAGES * 32768)

__device__ __forceinline__ void gemm_issue_stage(
    uint32_t stage, const h16* __restrict__ Ah, const h16* __restrict__ Bh,
    int M, int N, int Kd, int bm, int bn, int k0, int tid, int amap) {
    int arow = tid >> 1, akc = (tid & 1) << 5;   // 32 halves = 64B per thread
    int m = bm + arow;
    int avalid = (m < M) ? 16 : 0;
    int srcRow;
    if (amap) { int j = m / amap, t = m % amap; srcRow = j * TT + (TT - amap) + t; }
    else srcRow = m;
    size_t arIdx = (size_t)(avalid ? srcRow : 0);
    const h16* agh = Ah + arIdx * Kd + k0 + akc;
    #pragma unroll
    for (int u = 0; u < 4; u++)
        cp16(stage + swiz128(arow * 128 + (akc + 8 * u) * 2), agh + 8 * u, avalid);
    int bk = tid >> 2, bnc = (tid & 3) << 5;     // 64 rows x 256B; 32 cols/thread
    const h16* bgh = Bh + (size_t)(k0 + bk) * N + bn + bnc;
    #pragma unroll
    for (int u = 0; u < 4; u++)
        cp16(stage + 16384u + swizB(bk, bnc + 8 * u), bgh + 8 * u, 16);
}

__global__ void __launch_bounds__(256)
gemm_tc_kernel(const h16* __restrict__ Ah, const h16* __restrict__ Bh,
               const float* __restrict__ bias,
               const float* __restrict__ resid, int rmode,
               float* __restrict__ Cm, h16* __restrict__ Ch,
               int M, int N, int Kd, int act, int amap) {
    extern __shared__ __align__(16) char sm[];
    uint32_t sb = (uint32_t)__cvta_generic_to_shared(sm);
    const int tid  = threadIdx.x;
    const int lane = tid & 31;
    const int w    = tid >> 5;
    const int wm   = w & 1;
    const int wn   = w >> 1;
    const int bm   = blockIdx.y * 128;
    const int bn   = blockIdx.x * 128;

    int aOff[4][4], bOff[2][4];
    {
        int ar = wm * 64 + (lane & 15);
        int ac = (lane >> 4) << 3;
        #pragma unroll
        for (int i = 0; i < 4; i++)
            #pragma unroll
            for (int s = 0; s < 4; s++)
                aOff[i][s] = swiz128((ar + 16 * i) * 128 + (16 * s + ac) * 2);
        int bk  = lane & 15;
        int bn0 = wn * 32 + ((lane >> 4) << 3);
        #pragma unroll
        for (int jp = 0; jp < 2; jp++)
            #pragma unroll
            for (int s = 0; s < 4; s++)
                bOff[jp][s] = 16384 + swizB(bk + 16 * s, bn0 + 16 * jp);
    }

    float acc[4][4][4];
    #pragma unroll
    for (int i = 0; i < 4; i++)
        #pragma unroll
        for (int j = 0; j < 4; j++)
            #pragma unroll
            for (int r = 0; r < 4; r++) acc[i][j][r] = 0.f;

    const int nCh = Kd >> 6;
    #pragma unroll
    for (int p = 0; p < GEMM_STAGES - 1; p++) {
        gemm_issue_stage(sb + (uint32_t)p * STAGE_BYTES, Ah, Bh,
                         M, N, Kd, bm, bn, p << 6, tid, amap);
        asm volatile("cp.async.commit_group;");
    }

    for (int kc = 0; kc < nCh; kc++) {
        asm volatile("cp.async.wait_group %0;" :: "n"(GEMM_STAGES - 2));
        __syncthreads();
        int pf = kc + GEMM_STAGES - 1;
        if (pf < nCh)
            gemm_issue_stage(sb + (uint32_t)(pf % GEMM_STAGES) * STAGE_BYTES,
                             Ah, Bh, M, N, Kd, bm, bn, pf << 6, tid, amap);
        asm volatile("cp.async.commit_group;");

        uint32_t stage = sb + (uint32_t)(kc % GEMM_STAGES) * STAGE_BYTES;
        #pragma unroll
        for (int s = 0; s < 4; s++) {
            uint32_t ah[4][4], bh[2][4];
            #pragma unroll
            for (int i = 0; i < 4; i++)
                LDSM4(ah[i], stage + aOff[i][s]);
            #pragma unroll
            for (int jp = 0; jp < 2; jp++)
                LDSM4T(bh[jp], stage + bOff[jp][s]);
            #pragma unroll
            for (int i = 0; i < 4; i++) {
                #pragma unroll
                for (int j = 0; j < 4; j++) {
                    const uint32_t* bhj = &bh[j >> 1][(j & 1) * 2];
                    MMA_F16(acc[i][j], ah[i], bhj[0], bhj[1]);
                }
            }
        }
    }

    // epilogue
    #pragma unroll
    for (int i = 0; i < 4; i++) {
        int r0 = bm + wm * 64 + i * 16 + (lane >> 2);
        #pragma unroll
        for (int j = 0; j < 4; j++) {
            int c0 = bn + wn * 32 + j * 8 + (lane & 3) * 2;
            float b0 = bias ? bias[c0] : 0.f;
            float b1 = bias ? bias[c0 + 1] : 0.f;
            float v0 = acc[i][j][0] + b0, v1 = acc[i][j][1] + b1;
            float v2 = acc[i][j][2] + b0, v3 = acc[i][j][3] + b1;
            if (act == 1) {
                v0 = 0.5f * v0 * (1.f + erff(v0 * 0.70710678118654752f));
                v1 = 0.5f * v1 * (1.f + erff(v1 * 0.70710678118654752f));
                v2 = 0.5f * v2 * (1.f + erff(v2 * 0.70710678118654752f));
                v3 = 0.5f * v3 * (1.f + erff(v3 * 0.70710678118654752f));
            }
            if (rmode) {
                if (r0 < M) {
                    const float* rp = (rmode == 1)
                        ? resid + (size_t)r0 * N + c0
                        : resid + ((size_t)(r0 / KT) * LSEQ + 1 + (r0 % KT)) * CDIM + c0;
                    v0 += rp[0]; v1 += rp[1];
                }
                if (r0 + 8 < M) {
                    int r8 = r0 + 8;
                    const float* rp = (rmode == 1)
                        ? resid + (size_t)r8 * N + c0
                        : resid + ((size_t)(r8 / KT) * LSEQ + 1 + (r8 % KT)) * CDIM + c0;
                    v2 += rp[0]; v3 += rp[1];
                }
            }
            if (Ch) {
                if (r0 < M) {
                    uint32_t p = (uint32_t)__half_as_ushort(__float2half_rn(v0))
                               | ((uint32_t)__half_as_ushort(__float2half_rn(v1)) << 16);
                    *(uint32_t*)&Ch[(size_t)r0 * N + c0] = p;
                }
                if (r0 + 8 < M) {
                    uint32_t p = (uint32_t)__half_as_ushort(__float2half_rn(v2))
                               | ((uint32_t)__half_as_ushort(__float2half_rn(v3)) << 16);
                    *(uint32_t*)&Ch[(size_t)(r0 + 8) * N + c0] = p;
                }
            } else {
                if (r0 < M)     *(float2*)&Cm[(size_t)r0 * N + c0]       = make_float2(v0, v1);
                if (r0 + 8 < M) *(float2*)&Cm[(size_t)(r0 + 8) * N + c0] = make_float2(v2, v3);
            }
        }
    }
}

// ======================= fused temporal attention (MMA, L <= 16) =============
__global__ void __launch_bounds__(256)
attn_tmp_kernel(const h16* __restrict__ qkv, h16* __restrict__ outp, int L) {
    __shared__ __align__(16) char sm[8 * 3 * 2048];
    const int tid = threadIdx.x, lane = tid & 31, w = tid >> 5;
    const int g = blockIdx.x * 8 + w;
    const int s = g / NHEAD, h = g % NHEAD;
    uint32_t base = (uint32_t)__cvta_generic_to_shared(sm) + (uint32_t)w * 6144u;
    const h16* src0 = qkv + (size_t)s * L * 3 * CDIM + h * HDIM;

    for (int i = lane; i < 3 * 128; i += 32) {
        int p = i >> 7;
        int rem = i & 127;
        int tok = rem >> 3, c8 = rem & 7;
        uint4 v = make_uint4(0u, 0u, 0u, 0u);
        if (tok < L)
            v = *(const uint4*)(src0 + (size_t)tok * 3 * CDIM + p * CDIM + c8 * 8);
        *(uint4*)(sm + w * 6144 + p * 2048 + swiz128(tok * 128 + c8 * 16)) = v;
    }
    __syncwarp();

    const uint32_t Qb = base, Kb = base + 2048u, Vb = base + 4096u;
    const int lr = lane & 15, lc = (lane >> 4) * 8;
    const int c2 = (lane & 3) * 2;

    float sacc[2][4];
    #pragma unroll
    for (int n = 0; n < 2; n++)
        #pragma unroll
        for (int e = 0; e < 4; e++) sacc[n][e] = 0.f;
    #pragma unroll
    for (int kc = 0; kc < 4; kc++) {
        uint32_t qf[4], kf[4];
        LDSM4(qf, Qb + swiz128(lr * 128 + (lc + kc * 16) * 2));
        LDSM4(kf, Kb + swiz128(lr * 128 + (lc + kc * 16) * 2));
        MMA_F16(sacc[0], qf, kf[0], kf[2]);
        MMA_F16(sacc[1], qf, kf[1], kf[3]);
    }
    #pragma unroll
    for (int nt = 0; nt < 2; nt++) {
        int nb = nt * 8 + c2;
        sacc[nt][0] = (nb     < L) ? sacc[nt][0] * ATT_SCALE : -1e30f;
        sacc[nt][1] = (nb + 1 < L) ? sacc[nt][1] * ATT_SCALE : -1e30f;
        sacc[nt][2] = (nb     < L) ? sacc[nt][2] * ATT_SCALE : -1e30f;
        sacc[nt][3] = (nb + 1 < L) ? sacc[nt][3] * ATT_SCALE : -1e30f;
    }
    float bm0 = fmaxf(fmaxf(sacc[0][0], sacc[0][1]), fmaxf(sacc[1][0], sacc[1][1]));
    float bm1 = fmaxf(fmaxf(sacc[0][2], sacc[0][3]), fmaxf(sacc[1][2], sacc[1][3]));
    bm0 = fmaxf(bm0, __shfl_xor_sync(0xffffffffu, bm0, 1));
    bm0 = fmaxf(bm0, __shfl_xor_sync(0xffffffffu, bm0, 2));
    bm1 = fmaxf(bm1, __shfl_xor_sync(0xffffffffu, bm1, 1));
    bm1 = fmaxf(bm1, __shfl_xor_sync(0xffffffffu, bm1, 2));
    uint32_t af[4];
    float ps0 = 0.f, ps1 = 0.f;
    #pragma unroll
    for (int nt = 0; nt < 2; nt++) {
        h16 p0 = __float2half_rn(__expf(sacc[nt][0] - bm0));
        h16 p1 = __float2half_rn(__expf(sacc[nt][1] - bm0));
        h16 p2 = __float2half_rn(__expf(sacc[nt][2] - bm1));
        h16 p3 = __float2half_rn(__expf(sacc[nt][3] - bm1));
        af[nt * 2]     = (uint32_t)__half_as_ushort(p0) | ((uint32_t)__half_as_ushort(p1) << 16);
        af[nt * 2 + 1] = (uint32_t)__half_as_ushort(p2) | ((uint32_t)__half_as_ushort(p3) << 16);
        ps0 += __half2float(p0) + __half2float(p1);
        ps1 += __half2float(p2) + __half2float(p3);
    }
    ps0 += __shfl_xor_sync(0xffffffffu, ps0, 1);
    ps0 += __shfl_xor_sync(0xffffffffu, ps0, 2);
    ps1 += __shfl_xor_sync(0xffffffffu, ps1, 1);
    ps1 += __shfl_xor_sync(0xffffffffu, ps1, 2);

    float o[8][4];
    #pragma unroll
    for (int n = 0; n < 8; n++)
        #pragma unroll
        for (int e = 0; e < 4; e++) o[n][e] = 0.f;
    #pragma unroll
    for (int vd = 0; vd < 4; vd++) {
        uint32_t vf[4];
        LDSM4T(vf, Vb + swiz128(lr * 128 + (lc + vd * 16) * 2));
        MMA_F16(o[vd * 2],     af, vf[0], vf[1]);
        MMA_F16(o[vd * 2 + 1], af, vf[2], vf[3]);
    }

    float inv0 = 1.f / ps0, inv1 = 1.f / ps1;
    int q0 = lane >> 2, q1 = q0 + 8;
    #pragma unroll
    for (int n = 0; n < 8; n++) {
        int dim = n * 8 + c2;
        if (q0 < L) {
            uint32_t p = (uint32_t)__half_as_ushort(__float2half_rn(o[n][0] * inv0))
                       | ((uint32_t)__half_as_ushort(__float2half_rn(o[n][1] * inv0)) << 16);
            *(uint32_t*)&outp[((size_t)s * L + q0) * CDIM + h * HDIM + dim] = p;
        }
        if (q1 < L) {
            uint32_t p = (uint32_t)__half_as_ushort(__float2half_rn(o[n][2] * inv1))
                       | ((uint32_t)__half_as_ushort(__float2half_rn(o[n][3] * inv1)) << 16);
            *(uint32_t*)&outp[((size_t)s * L + q1) * CDIM + h * HDIM + dim] = p;
        }
    }
}

// ======================= fused spatial flash attention =======================
#define FLP 208
#define FNB 13
#define FQKV_BYTES 26624
#define FLASH_SMEM (3 * FQKV_BYTES)

__global__ void __launch_bounds__(256)
flash_sp_kernel(const h16* __restrict__ qkvh, h16* __restrict__ outp) {
    extern __shared__ __align__(16) char sm[];
    uint32_t sb = (uint32_t)__cvta_generic_to_shared(sm);
    const int bh = blockIdx.x;
    const int s = bh / NHEAD, h = bh % NHEAD;
    const int tid = threadIdx.x, lane = tid & 31, w = tid >> 5;

    for (int i = tid; i < 3 * FLP * 8; i += 256) {
        int p = i / (FLP * 8);
        int rem = i % (FLP * 8);
        int tok = rem >> 3, c8 = rem & 7;
        uint4 v = make_uint4(0u, 0u, 0u, 0u);
        if (tok < LSP) {
            const h16* src = qkvh + ((size_t)(s * LSP + tok)) * (3 * CDIM)
                           + p * CDIM + h * HDIM + c8 * 8;
            v = *(const uint4*)src;
        }
        *(uint4*)(sm + p * FQKV_BYTES + swiz128(tok * 128 + c8 * 16)) = v;
    }
    __syncthreads();
    const uint32_t Qb = sb, Kb = sb + FQKV_BYTES, Vb = sb + 2u * FQKV_BYTES;

    const int lr = lane & 15, lc = (lane >> 4) * 8;
    const int c2 = (lane & 3) * 2;

    for (int qt = w; qt < FNB; qt += 8) {
        uint32_t qf[4][4];
        #pragma unroll
        for (int kc = 0; kc < 4; kc++)
            LDSM4(qf[kc], Qb + swiz128((qt * 16 + lr) * 128 + (lc + kc * 16) * 2));

        float o[8][4];
        #pragma unroll
        for (int n = 0; n < 8; n++)
            #pragma unroll
            for (int e = 0; e < 4; e++) o[n][e] = 0.f;
        float m0 = -1e30f, m1 = -1e30f, l0 = 0.f, l1 = 0.f;

        for (int blk = 0; blk < FNB; blk++) {
            float sacc[2][4];
            #pragma unroll
            for (int n = 0; n < 2; n++)
                #pragma unroll
                for (int e = 0; e < 4; e++) sacc[n][e] = 0.f;
            #pragma unroll
            for (int kc = 0; kc < 4; kc++) {
                uint32_t kf[4];
                LDSM4(kf, Kb + swiz128((blk * 16 + lr) * 128 + (lc + kc * 16) * 2));
                MMA_F16(sacc[0], qf[kc], kf[0], kf[2]);
                MMA_F16(sacc[1], qf[kc], kf[1], kf[3]);
            }
            #pragma unroll
            for (int nt = 0; nt < 2; nt++) {
                int nb = blk * 16 + nt * 8 + c2;
                sacc[nt][0] = (nb     < LSP) ? sacc[nt][0] * ATT_SCALE : -1e30f;
                sacc[nt][1] = (nb + 1 < LSP) ? sacc[nt][1] * ATT_SCALE : -1e30f;
                sacc[nt][2] = (nb     < LSP) ? sacc[nt][2] * ATT_SCALE : -1e30f;
                sacc[nt][3] = (nb + 1 < LSP) ? sacc[nt][3] * ATT_SCALE : -1e30f;
            }
            float bm0 = fmaxf(fmaxf(sacc[0][0], sacc[0][1]), fmaxf(sacc[1][0], sacc[1][1]));
            float bm1 = fmaxf(fmaxf(sacc[0][2], sacc[0][3]), fmaxf(sacc[1][2], sacc[1][3]));
            bm0 = fmaxf(bm0, __shfl_xor_sync(0xffffffffu, bm0, 1));
            bm0 = fmaxf(bm0, __shfl_xor_sync(0xffffffffu, bm0, 2));
            bm1 = fmaxf(bm1, __shfl_xor_sync(0xffffffffu, bm1, 1));
            bm1 = fmaxf(bm1, __shfl_xor_sync(0xffffffffu, bm1, 2));
            float mn0 = fmaxf(m0, bm0), mn1 = fmaxf(m1, bm1);
            float a0 = __expf(m0 - mn0), a1 = __expf(m1 - mn1);
            m0 = mn0; m1 = mn1;
            l0 *= a0; l1 *= a1;
            #pragma unroll
            for (int n = 0; n < 8; n++) {
                o[n][0] *= a0; o[n][1] *= a0;
                o[n][2] *= a1; o[n][3] *= a1;
            }
            uint32_t af[4];
            float ps0 = 0.f, ps1 = 0.f;
            #pragma unroll
            for (int nt = 0; nt < 2; nt++) {
                h16 p0 = __float2half_rn(__expf(sacc[nt][0] - mn0));
                h16 p1 = __float2half_rn(__expf(sacc[nt][1] - mn0));
                h16 p2 = __float2half_rn(__expf(sacc[nt][2] - mn1));
                h16 p3 = __float2half_rn(__expf(sacc[nt][3] - mn1));
                af[nt * 2]     = (uint32_t)__half_as_ushort(p0)
                               | ((uint32_t)__half_as_ushort(p1) << 16);
                af[nt * 2 + 1] = (uint32_t)__half_as_ushort(p2)
                               | ((uint32_t)__half_as_ushort(p3) << 16);
                ps0 += __half2float(p0) + __half2float(p1);
                ps1 += __half2float(p2) + __half2float(p3);
            }
            ps0 += __shfl_xor_sync(0xffffffffu, ps0, 1);
            ps0 += __shfl_xor_sync(0xffffffffu, ps0, 2);
            ps1 += __shfl_xor_sync(0xffffffffu, ps1, 1);
            ps1 += __shfl_xor_sync(0xffffffffu, ps1, 2);
            l0 += ps0; l1 += ps1;
            #pragma unroll
            for (int vd = 0; vd < 4; vd++) {
                uint32_t vf[4];
                LDSM4T(vf, Vb + swiz128((blk * 16 + lr) * 128 + (lc + vd * 16) * 2));
                MMA_F16(o[vd * 2],     af, vf[0], vf[1]);
                MMA_F16(o[vd * 2 + 1], af, vf[2], vf[3]);
            }
        }
        float inv0 = 1.f / l0, inv1 = 1.f / l1;
        int q0 = qt * 16 + (lane >> 2), q1 = q0 + 8;
        #pragma unroll
        for (int n = 0; n < 8; n++) {
            int dim = n * 8 + c2;
            if (q0 < LSP) {
                uint32_t p = (uint32_t)__half_as_ushort(__float2half_rn(o[n][0] * inv0))
                           | ((uint32_t)__half_as_ushort(__float2half_rn(o[n][1] * inv0)) << 16);
                *(uint32_t*)&outp[((size_t)(s * LSP + q0)) * CDIM + h * HDIM + dim] = p;
            }
            if (q1 < LSP) {
                uint32_t p = (uint32_t)__half_as_ushort(__float2half_rn(o[n][2] * inv1))
                           | ((uint32_t)__half_as_ushort(__float2half_rn(o[n][3] * inv1)) << 16);
                *(uint32_t*)&outp[((size_t)(s * LSP + q1)) * CDIM + h * HDIM + dim] = p;
            }
        }
    }
}

// ------------------------- LayerNorm primitives -----------------------------
__device__ __forceinline__ float2 ln_stats_val(float s, float ss) {
    __shared__ float sm0[8], sm1[8];
    #pragma unroll
    for (int o = 16; o > 0; o >>= 1) {
        s  += __shfl_down_sync(0xffffffffu, s,  o);
        ss += __shfl_down_sync(0xffffffffu, ss, o);
    }
    int w = threadIdx.x >> 5;
    if ((threadIdx.x & 31) == 0) { sm0[w] = s; sm1[w] = ss; }
    __syncthreads();
    if (threadIdx.x == 0) {
        float a = 0.f, b2 = 0.f;
        int nw = blockDim.x >> 5;
        for (int i = 0; i < nw; i++) { a += sm0[i]; b2 += sm1[i]; }
        sm0[0] = a; sm1[0] = b2;
    }
    __syncthreads();
    float mean = sm0[0] * (1.f / CDIM);
    float var  = sm1[0] * (1.f / CDIM) - mean * mean;
    return make_float2(mean, rsqrtf(var + 1e-5f));
}

__device__ __forceinline__ float2 ln_stats(const float* __restrict__ src) {
    float s = 0.f, ss = 0.f;
    for (int c = threadIdx.x; c < CDIM; c += blockDim.x) {
        float v = src[c];
        s += v; ss += v * v;
    }
    return ln_stats_val(s, ss);
}

__device__ __forceinline__ void ln_row(const float* __restrict__ src,
                                       float* __restrict__ dst,
                                       const float* __restrict__ g,
                                       const float* __restrict__ bta) {
    float2 st = ln_stats(src);
    for (int c = threadIdx.x; c < CDIM; c += blockDim.x)
        dst[c] = (src[c] - st.x) * st.y * g[c] + bta[c];
}

__device__ __forceinline__ void ln_row_h(const float* __restrict__ src,
                                         h16* __restrict__ dh,
                                         const float* __restrict__ g,
                                         const float* __restrict__ bta) {
    float2 st = ln_stats(src);
    for (int c = threadIdx.x; c < CDIM; c += blockDim.x)
        dh[c] = __float2half_rn((src[c] - st.x) * st.y * g[c] + bta[c]);
}

__global__ void ln_xt_kernel(const float* __restrict__ x, h16* __restrict__ oh,
                             const float* __restrict__ g, const float* __restrict__ b) {
    int r = blockIdx.x;
    int bb = r / KT, off = r % KT;
    ln_row_h(x + ((size_t)bb * LSEQ + 1 + off) * CDIM, oh + (size_t)r * CDIM, g, b);
}

__global__ void ln_cls_kernel(const float* __restrict__ in, float* __restrict__ out,
                              const float* __restrict__ g, const float* __restrict__ b) {
    int r = blockIdx.x;
    ln_row(in + (size_t)r * LSP * CDIM, out + (size_t)r * CDIM, g, b);
}

__global__ void build_xs_ln_kernel(const float* __restrict__ x, const float* __restrict__ xtfull,
                                   const float* __restrict__ g, const float* __restrict__ bta,
                                   h16* __restrict__ oh) {
    int r = blockIdx.x;
    int s = r / LSP, i = r % LSP;
    int bb = s / TT, t = s % TT;
    const float* src = (i == 0)
        ? (x + (size_t)bb * LSEQ * CDIM)
        : (xtfull + ((size_t)bb * KT + (size_t)(i - 1) * TT + t) * CDIM);
    ln_row_h(src, oh + (size_t)r * CDIM, g, bta);
}

__global__ void build_xcat_ln_kernel(const float* __restrict__ x, const float* __restrict__ xtfull,
                                     const float* __restrict__ ressp, const float* __restrict__ clsout,
                                     const float* __restrict__ g, const float* __restrict__ bta,
                                     float* __restrict__ xcat, h16* __restrict__ oh) {
    int r = blockIdx.x;
    int bb = r / LSEQ, i = r % LSEQ;
    float v[3];
    float s = 0.f, ss = 0.f;
    #pragma unroll
    for (int e = 0; e < 3; e++) {
        int c = threadIdx.x + e * 256;
        float val;
        if (i == 0) {
            val = x[(size_t)bb * LSEQ * CDIM + c] + clsout[(size_t)bb * CDIM + c];
        } else {
            int n = i - 1;
            int k = n / TT, t = n % TT;
            val = xtfull[((size_t)bb * KT + n) * CDIM + c]
                + ressp[(((size_t)(bb * TT + t)) * LSP + 1 + k) * CDIM + c];
        }
        v[e] = val;
        xcat[(size_t)r * CDIM + c] = val;
        s += val; ss += val * val;
    }
    float2 st = ln_stats_val(s, ss);
    #pragma unroll
    for (int e = 0; e < 3; e++) {
        int c = threadIdx.x + e * 256;
        oh[(size_t)r * CDIM + c] = __float2half_rn((v[e] - st.x) * st.y * g[c] + bta[c]);
    }
}

// ------------------------- pointwise steps ----------------------------------
__global__ void combine_kernel(const float* __restrict__ x16, const float* __restrict__ x8,
                               const float* __restrict__ x4, h16* __restrict__ oh) {
    size_t idx = (size_t)blockIdx.x * blockDim.x + threadIdx.x;
    size_t tot = (size_t)MT * CDIM;
    if (idx >= tot) return;
    int c = (int)(idx % CDIM);
    size_t row = idx / CDIM;
    int j = (int)(row / TT), t = (int)(row % TT);
    float v = x16[idx];
    if (t >= 8) {
        float v8 = x8[((size_t)j * 8 + (t - 8)) * CDIM + c];
        if (t >= 12) v8 = 0.5f * v8 + 0.5f * x4[((size_t)j * 4 + (t - 12)) * CDIM + c];
        v = 0.5f * v + 0.5f * v8;
    }
    oh[idx] = __float2half_rn(v);
}

__global__ void cls_attn_kernel(const float* __restrict__ clssp, float* __restrict__ out) {
    int b = blockIdx.x;
    __shared__ float dots[TT];
    __shared__ float wts[TT];
    int w = threadIdx.x >> 5, lane = threadIdx.x & 31;
    const float* base = clssp + (size_t)b * TT * CDIM;
    const float* tgt = base + (size_t)(TT - 1) * CDIM;
    for (int t = w; t < TT; t += 8) {
        float sd = 0.f;
        for (int c = lane; c < CDIM; c += 32) sd = fmaf(tgt[c], base[(size_t)t * CDIM + c], sd);
        #pragma unroll
        for (int o = 16; o > 0; o >>= 1) sd += __shfl_xor_sync(0xffffffffu, sd, o);
        if (lane == 0) dots[t] = sd;
    }
    __syncthreads();
    if (threadIdx.x == 0) {
        float mx = -1e30f;
        for (int t = 0; t < TT; t++) mx = fmaxf(mx, dots[t]);
        float s = 0.f;
        for (int t = 0; t < TT; t++) { float e = expf(dots[t] - mx); wts[t] = e; s += e; }
        float inv = 1.f / s;
        for (int t = 0; t < TT; t++) wts[t] *= inv;
    }
    __syncthreads();
    for (int c = threadIdx.x; c < CDIM; c += blockDim.x) {
        float a = 0.f;
        #pragma unroll
        for (int t = 0; t < TT; t++) a = fmaf(wts[t], base[(size_t)t * CDIM + c], a);
        out[(size_t)b * CDIM + c] = a;
    }
}

// ------------------------- host orchestration -------------------------------
static inline void gemm5(cudaStream_t stm, const h16* Ah, const h16* Bh, const float* bias,
                         const float* resid, int rmode,
                         float* C, h16* Ch, int M, int N, int K, int act, int amap) {
    dim3 blk(256);
    dim3 grd(N / 128, (M + 127) / 128);
    gemm_tc_kernel<<<grd, blk, GEMM_SMEM, stm>>>(Ah, Bh, bias, resid, rmode, C, Ch,
                                                 M, N, K, act, amap);
}

extern "C" void kernel_launch(void* const* d_in, const int* in_sizes, int n_in,
                              void* d_out, int out_size) {
    const float* x       = (const float*)d_in[0];
    const float* ln1_g   = (const float*)d_in[4];
    const float* ln1_b   = (const float*)d_in[5];
    const float* lnt_g   = (const float*)d_in[6];
    const float* lnt_b   = (const float*)d_in[7];
    const float* ln2_g   = (const float*)d_in[8];
    const float* ln2_b   = (const float*)d_in[9];
    const float* lncls_g = (const float*)d_in[10];
    const float* lncls_b = (const float*)d_in[11];
    const float* Wqkv_s  = (const float*)d_in[12];
    const float* Wproj_s = (const float*)d_in[13];
    const float* bproj_s = (const float*)d_in[14];
    const float* Wqkv4   = (const float*)d_in[15];
    const float* Wqkv8   = (const float*)d_in[16];
    const float* Wqkv16  = (const float*)d_in[17];
    const float* Wp4     = (const float*)d_in[18];
    const float* bp4     = (const float*)d_in[19];
    const float* Wp8     = (const float*)d_in[20];
    const float* bp8     = (const float*)d_in[21];
    const float* Wp16    = (const float*)d_in[22];
    const float* bp16    = (const float*)d_in[23];
    const float* Wtfc    = (const float*)d_in[24];
    const float* btfc    = (const float*)d_in[25];
    const float* Wfc1    = (const float*)d_in[26];
    const float* bfc1    = (const float*)d_in[27];
    const float* Wfc2    = (const float*)d_in[28];
    const float* bfc2    = (const float*)d_in[29];
    float* out = (float*)d_out;

    static cudaStream_t st[3];
    static cudaEvent_t  ev[4];
    static int inited = 0;
    if (!inited) {
        for (int i = 0; i < 3; i++)
            cudaStreamCreateWithFlags(&st[i], cudaStreamNonBlocking);
        for (int i = 0; i < 4; i++)
            cudaEventCreateWithFlags(&ev[i], cudaEventDisableTiming);
        cudaFuncSetAttribute(gemm_tc_kernel,
                             cudaFuncAttributeMaxDynamicSharedMemorySize, GEMM_SMEM);
        cudaFuncSetAttribute(flash_sp_kernel,
                             cudaFuncAttributeMaxDynamicSharedMemorySize, FLASH_SMEM);
        inited = 1;
    }

    float *x16, *x8, *x4, *xtfull, *ressp, *clssp, *clsout, *xcat;
    h16 *pah, *pbh, *pbh8, *pbh4, *pch, *h1h, *wh, *qkvh, *qkvh8, *qkvh4;
    cudaGetSymbolAddress((void**)&x16,    g_x16);
    cudaGetSymbolAddress((void**)&x8,     g_x8);
    cudaGetSymbolAddress((void**)&x4,     g_x4);
    cudaGetSymbolAddress((void**)&xtfull, g_xtfull);
    cudaGetSymbolAddress((void**)&ressp,  g_ressp);
    cudaGetSymbolAddress((void**)&clssp,  g_clssp);
    cudaGetSymbolAddress((void**)&clsout, g_clsout);
    cudaGetSymbolAddress((void**)&xcat,   g_xcat);
    cudaGetSymbolAddress((void**)&pah,    g_pah);
    cudaGetSymbolAddress((void**)&pbh,    g_pbh);
    cudaGetSymbolAddress((void**)&pbh8,   g_pbh8);
    cudaGetSymbolAddress((void**)&pbh4,   g_pbh4);
    cudaGetSymbolAddress((void**)&pch,    g_pch);
    cudaGetSymbolAddress((void**)&h1h,    g_h1h);
    cudaGetSymbolAddress((void**)&wh,     g_wh);
    cudaGetSymbolAddress((void**)&qkvh,   g_qkvh);
    cudaGetSymbolAddress((void**)&qkvh8,  g_qkvh8);
    cudaGetSymbolAddress((void**)&qkvh4,  g_qkvh4);

    // 0) weight fp16 conversion — single launch
    {
        WPack p;
        const float* srcs[11] = {Wqkv_s, Wqkv4, Wqkv8, Wqkv16, Wproj_s, Wp4,
                                 Wp8, Wp16, Wtfc, Wfc1, Wfc2};
        unsigned offs[11] = {OFF_QKV_S, OFF_QKV4, OFF_QKV8, OFF_QKV16, OFF_P_S,
                             OFF_P4, OFF_P8, OFF_P16, OFF_TFC, OFF_FC1, OFF_FC2};
        unsigned n4s[11] = {442368u, 442368u, 442368u, 442368u, 147456u,
                            147456u, 147456u, 147456u, 147456u, 589824u, 589824u};
        for (int i = 0; i < 11; i++) { p.src[i] = srcs[i]; p.dstoff[i] = offs[i]; p.n4[i] = n4s[i]; }
        convW_all_kernel<<<dim3(2304, 11), 256>>>(p, wh);
    }

    // 1) LN over temporal sequences -> fp16 plane
    ln_xt_kernel<<<MT, 256>>>(x, pah, lnt_g, lnt_b);

    // 2) Temporal MHAs — 3 independent chains on 3 streams
    cudaEventRecord(ev[3], 0);
    for (int i = 0; i < 3; i++) cudaStreamWaitEvent(st[i], ev[3], 0);

    // chain 16 (stream 0)
    gemm5(st[0], pah, wh + OFF_QKV16, nullptr, nullptr, 0, nullptr, qkvh,
          MT, 3 * CDIM, CDIM, 0, 0);
    attn_tmp_kernel<<<(BKR * NHEAD) / 8, 256, 0, st[0]>>>(qkvh, pbh, 16);
    gemm5(st[0], pbh, wh + OFF_P16, bp16, nullptr, 0, x16, nullptr,
          MT, CDIM, CDIM, 0, 0);
    cudaEventRecord(ev[0], st[0]);

    // chain 8 (stream 1)
    gemm5(st[1], pah, wh + OFF_QKV8, nullptr, nullptr, 0, nullptr, qkvh8,
          BKR * 8, 3 * CDIM, CDIM, 0, 8);
    attn_tmp_kernel<<<(BKR * NHEAD) / 8, 256, 0, st[1]>>>(qkvh8, pbh8, 8);
    gemm5(st[1], pbh8, wh + OFF_P8, bp8, nullptr, 0, x8, nullptr,
          BKR * 8, CDIM, CDIM, 0, 0);
    cudaEventRecord(ev[1], st[1]);

    // chain 4 (stream 2)
    gemm5(st[2], pah, wh + OFF_QKV4, nullptr, nullptr, 0, nullptr, qkvh4,
          BKR * 4, 3 * CDIM, CDIM, 0, 4);
    attn_tmp_kernel<<<(BKR * NHEAD) / 8, 256, 0, st[2]>>>(qkvh4, pbh4, 4);
    gemm5(st[2], pbh4, wh + OFF_P4, bp4, nullptr, 0, x4, nullptr,
          BKR * 4, CDIM, CDIM, 0, 0);
    cudaEventRecord(ev[2], st[2]);

    for (int i = 0; i < 3; i++) cudaStreamWaitEvent(0, ev[i], 0);

    // 3) Blend scales -> fp16 plane
    {
        size_t tot = (size_t)MT * CDIM;
        combine_kernel<<<(int)((tot + 255) / 256), 256>>>(x16, x8, x4, pch);
    }

    // 4) xt_full = blend @ Wtfc + btfc + x residual (fused epilogue)
    gemm5(0, pch, wh + OFF_TFC, btfc, x, 2, xtfull, nullptr, MT, CDIM, CDIM, 0, 0);

    // 5) Spatial MHA: LN -> qkv(fp16) -> flash -> proj
    build_xs_ln_kernel<<<MSP, 256>>>(x, xtfull, ln1_g, ln1_b, pah);
    gemm5(0, pah, wh + OFF_QKV_S, nullptr, nullptr, 0, nullptr, qkvh,
          MSP, 3 * CDIM, CDIM, 0, 0);
    flash_sp_kernel<<<SSP * NHEAD, 256, FLASH_SMEM>>>(qkvh, pbh);
    gemm5(0, pbh, wh + OFF_P_S, bproj_s, nullptr, 0, ressp, nullptr,
          MSP, CDIM, CDIM, 0, 0);

    // 6) CLS path
    ln_cls_kernel<<<SSP, 256>>>(ressp, clssp, lncls_g, lncls_b);
    cls_attn_kernel<<<BBATCH, 256>>>(clssp, clsout);

    // 7) x_cat + LN2 fused
    build_xcat_ln_kernel<<<MOUT, 256>>>(x, xtfull, ressp, clsout, ln2_g, ln2_b, xcat, pah);

    // 8) MLP: fc1 (GELU, fp16 out) -> fc2 (+xcat residual, writes out)
    gemm5(0, pah, wh + OFF_FC1, bfc1, nullptr, 0, nullptr, h1h, MOUT, HID, CDIM, 1, 0);
    gemm5(0, h1h, wh + OFF_FC2, bfc2, xcat, 1, out, nullptr, MOUT, CDIM, HID, 0, 0);
}

// round 16
// speedup vs baseline: 1.1166x; 1.1166x over previous
#include <cuda_runtime.h>
#include <cuda_fp16.h>
#include <math.h>
#include <stddef.h>
#include <stdint.h>

#define CDIM 768
#define NHEAD 12
#define HDIM 64
#define BBATCH 4
#define TT 16
#define KPATCH 196
#define LSEQ 3137           // 1 + K*T
#define BKR 784             // B*K
#define MT 12544            // BKR*TT
#define SSP 64              // B*T
#define LSP 197             // 1 + K
#define MSP 12608           // SSP*LSP
#define MOUT 12548          // B*LSEQ
#define HID 3072
#define KT 3136             // KPATCH*TT
#define ATT_SCALE 0.125f    // (64)^-0.5

typedef __half h16;

// ------------------------- device scratch (static, allocation-free) ---------
__device__ float g_xtfull[(size_t)MT   * CDIM];
__device__ float g_ressp [(size_t)MSP  * CDIM];
__device__ float g_clssp [(size_t)SSP  * CDIM];
__device__ float g_clsout[(size_t)BBATCH * CDIM];
__device__ float g_xcat  [(size_t)MOUT * CDIM];

// fp16 activation planes
#define PA_ELEMS ((size_t)MSP * CDIM)
__device__ h16 g_pah [PA_ELEMS];
__device__ h16 g_pbh [PA_ELEMS];
__device__ h16 g_pch [(size_t)MT * CDIM];
__device__ h16 g_h1h [(size_t)MOUT * HID];
__device__ h16 g_qkvh[(size_t)MSP * 3 * CDIM];   // qkv fp16 (temporal + spatial reuse)
__device__ h16 g_x16h[(size_t)MT * CDIM];
__device__ h16 g_x8h [(size_t)BKR * 8 * CDIM];
__device__ h16 g_x4h [(size_t)BKR * 4 * CDIM];

// weight plane (fp16), [K,N] row-major
#define WPOOL 14745600
__device__ h16 g_wh[(size_t)WPOOL];
#define OFF_QKV_S   0u
#define OFF_QKV4    1769472u
#define OFF_QKV8    3538944u
#define OFF_QKV16   5308416u
#define OFF_P_S     7077888u
#define OFF_P4      7667712u
#define OFF_P8      8257536u
#define OFF_P16     8847360u
#define OFF_TFC     9437184u
#define OFF_FC1    10027008u
#define OFF_FC2    12386304u

// ------------------------- weight conversion (single launch) ----------------
struct WPack {
    const float* src[11];
    unsigned dstoff[11];
    unsigned n4[11];
};

__global__ void convW_all_kernel(WPack p, h16* __restrict__ wh) {
    int s = blockIdx.y;
    unsigned i = blockIdx.x * 256u + threadIdx.x;
    if (i >= p.n4[s]) return;
    float4 v = ((const float4*)p.src[s])[i];
    unsigned short h0 = __half_as_ushort(__float2half_rn(v.x));
    unsigned short h1 = __half_as_ushort(__float2half_rn(v.y));
    unsigned short h2 = __half_as_ushort(__float2half_rn(v.z));
    unsigned short h3 = __half_as_ushort(__float2half_rn(v.w));
    ((uint2*)(wh + p.dstoff[s]))[i] =
        make_uint2((uint32_t)h0 | ((uint32_t)h1 << 16),
                   (uint32_t)h2 | ((uint32_t)h3 << 16));
}

// ------------------------- MMA primitives ------------------------------------
#define LDSM4(R, addr) \
    asm volatile("ldmatrix.sync.aligned.m8n8.x4.shared.b16 {%0,%1,%2,%3}, [%4];" \
                 : "=r"(R[0]), "=r"(R[1]), "=r"(R[2]), "=r"(R[3]) : "r"(addr))
#define LDSM4T(R, addr) \
    asm volatile("ldmatrix.sync.aligned.m8n8.x4.trans.shared.b16 {%0,%1,%2,%3}, [%4];" \
                 : "=r"(R[0]), "=r"(R[1]), "=r"(R[2]), "=r"(R[3]) : "r"(addr))
#define MMA_F16(d, a, b0, b1) \
    asm volatile("mma.sync.aligned.m16n8k16.row.col.f32.f16.f16.f32 " \
                 "{%0,%1,%2,%3}, {%4,%5,%6,%7}, {%8,%9}, {%0,%1,%2,%3};" \
                 : "+f"(d[0]), "+f"(d[1]), "+f"(d[2]), "+f"(d[3]) \
                 : "r"(a[0]), "r"(a[1]), "r"(a[2]), "r"(a[3]), "r"(b0), "r"(b1))

__device__ __forceinline__ int swizA(int r, int c) {
    int b = (r << 6) | (c << 1);
    return b ^ (((r >> 1) & 7) << 4);
}
__device__ __forceinline__ int swizB(int k, int n) {
    int b = (k << 8) | (n << 1);
    return b ^ ((k & 7) << 4);
}
__device__ __forceinline__ int swiz128(int boff) {
    return boff ^ ((boff >> 3) & 0x70);
}

__device__ __forceinline__ void cp16(uint32_t dst, const void* src, int sz) {
    asm volatile("cp.async.cg.shared.global [%0], [%1], 16, %2;"
                 :: "r"(dst), "l"(src), "r"(sz));
}

// ======================= tensor-core GEMM (fp16, BK=32) ======================
// rmode: 0 none, 1 resid[r*N+c], 2 resid = x with row map r -> bb*LSEQ+1+off
// amap : 0 identity, else Ts — A row m reads pah row (m/Ts)*TT + (TT-Ts) + m%Ts
#define GEMM_STAGES 5
#define STAGE_BYTES 16384u
#define GEMM_SMEM (GEMM_STAGES * 16384)

__device__ __forceinline__ void gemm_issue_stage(
    uint32_t stage, const h16* __restrict__ Ah, const h16* __restrict__ Bh,
    int M, int N, int Kd, int bm, int bn, int k0, int tid, int amap) {
    int arow = tid >> 1, akc = (tid & 1) << 4;
    int m = bm + arow;
    int avalid = (m < M) ? 16 : 0;
    int srcRow;
    if (amap) { int j = m / amap, t = m % amap; srcRow = j * TT + (TT - amap) + t; }
    else srcRow = m;
    size_t arIdx = (size_t)(avalid ? srcRow : 0);
    const h16* agh = Ah + arIdx * Kd + k0 + akc;
    uint32_t d0 = stage + swizA(arow, akc);
    uint32_t d1 = stage + swizA(arow, akc + 8);
    cp16(d0, agh, avalid);  cp16(d1, agh + 8, avalid);
    int bk = tid >> 3, bnc = (tid & 7) << 4;
    const h16* bgh = Bh + (size_t)(k0 + bk) * N + bn + bnc;
    uint32_t e0 = stage + 8192u + swizB(bk, bnc);
    uint32_t e1 = stage + 8192u + swizB(bk, bnc + 8);
    cp16(e0, bgh, 16);      cp16(e1, bgh + 8, 16);
}

__global__ void __launch_bounds__(256)
gemm_tc_kernel(const h16* __restrict__ Ah, const h16* __restrict__ Bh,
               const float* __restrict__ bias,
               const float* __restrict__ resid, int rmode,
               float* __restrict__ Cm, h16* __restrict__ Ch,
               int M, int N, int Kd, int act, int amap) {
    extern __shared__ __align__(16) char sm[];
    uint32_t sb = (uint32_t)__cvta_generic_to_shared(sm);
    const int tid  = threadIdx.x;
    const int lane = tid & 31;
    const int w    = tid >> 5;
    const int wm   = w & 1;
    const int wn   = w >> 1;
    const int bm   = blockIdx.y * 128;
    const int bn   = blockIdx.x * 128;

    int aOff[4][2], bOff[2][2];
    {
        int ar = wm * 64 + (lane & 15);
        int ac = (lane >> 4) << 3;
        #pragma unroll
        for (int i = 0; i < 4; i++)
            #pragma unroll
            for (int s = 0; s < 2; s++)
                aOff[i][s] = swizA(ar + 16 * i, ac + 16 * s);
        int bk  = lane & 15;
        int bn0 = wn * 32 + ((lane >> 4) << 3);
        #pragma unroll
        for (int jp = 0; jp < 2; jp++)
            #pragma unroll
            for (int s = 0; s < 2; s++)
                bOff[jp][s] = 8192 + swizB(bk + 16 * s, bn0 + 16 * jp);
    }

    float acc[4][4][4];
    #pragma unroll
    for (int i = 0; i < 4; i++)
        #pragma unroll
        for (int j = 0; j < 4; j++)
            #pragma unroll
            for (int r = 0; r < 4; r++) acc[i][j][r] = 0.f;

    const int nCh = Kd >> 5;
    #pragma unroll
    for (int p = 0; p < GEMM_STAGES - 1; p++) {
        gemm_issue_stage(sb + (uint32_t)p * STAGE_BYTES, Ah, Bh,
                         M, N, Kd, bm, bn, p << 5, tid, amap);
        asm volatile("cp.async.commit_group;");
    }

    for (int kc = 0; kc < nCh; kc++) {
        asm volatile("cp.async.wait_group %0;" :: "n"(GEMM_STAGES - 2));
        __syncthreads();
        int pf = kc + GEMM_STAGES - 1;
        if (pf < nCh)
            gemm_issue_stage(sb + (uint32_t)(pf % GEMM_STAGES) * STAGE_BYTES,
                             Ah, Bh, M, N, Kd, bm, bn, pf << 5, tid, amap);
        asm volatile("cp.async.commit_group;");

        uint32_t stage = sb + (uint32_t)(kc % GEMM_STAGES) * STAGE_BYTES;
        #pragma unroll
        for (int s = 0; s < 2; s++) {
            uint32_t ah[4][4], bh[2][4];
            #pragma unroll
            for (int i = 0; i < 4; i++)
                LDSM4(ah[i], stage + aOff[i][s]);
            #pragma unroll
            for (int jp = 0; jp < 2; jp++)
                LDSM4T(bh[jp], stage + bOff[jp][s]);
            #pragma unroll
            for (int i = 0; i < 4; i++) {
                #pragma unroll
                for (int j = 0; j < 4; j++) {
                    const uint32_t* bhj = &bh[j >> 1][(j & 1) * 2];
                    MMA_F16(acc[i][j], ah[i], bhj[0], bhj[1]);
                }
            }
        }
    }

    // epilogue
    #pragma unroll
    for (int i = 0; i < 4; i++) {
        int r0 = bm + wm * 64 + i * 16 + (lane >> 2);
        #pragma unroll
        for (int j = 0; j < 4; j++) {
            int c0 = bn + wn * 32 + j * 8 + (lane & 3) * 2;
            float b0 = bias ? bias[c0] : 0.f;
            float b1 = bias ? bias[c0 + 1] : 0.f;
            float v0 = acc[i][j][0] + b0, v1 = acc[i][j][1] + b1;
            float v2 = acc[i][j][2] + b0, v3 = acc[i][j][3] + b1;
            if (act == 1) {
                v0 = 0.5f * v0 * (1.f + erff(v0 * 0.70710678118654752f));
                v1 = 0.5f * v1 * (1.f + erff(v1 * 0.70710678118654752f));
                v2 = 0.5f * v2 * (1.f + erff(v2 * 0.70710678118654752f));
                v3 = 0.5f * v3 * (1.f + erff(v3 * 0.70710678118654752f));
            }
            if (rmode) {
                if (r0 < M) {
                    const float* rp = (rmode == 1)
                        ? resid + (size_t)r0 * N + c0
                        : resid + ((size_t)(r0 / KT) * LSEQ + 1 + (r0 % KT)) * CDIM + c0;
                    v0 += rp[0]; v1 += rp[1];
                }
                if (r0 + 8 < M) {
                    int r8 = r0 + 8;
                    const float* rp = (rmode == 1)
                        ? resid + (size_t)r8 * N + c0
                        : resid + ((size_t)(r8 / KT) * LSEQ + 1 + (r8 % KT)) * CDIM + c0;
                    v2 += rp[0]; v3 += rp[1];
                }
            }
            if (Ch) {
                if (r0 < M) {
                    uint32_t p = (uint32_t)__half_as_ushort(__float2half_rn(v0))
                               | ((uint32_t)__half_as_ushort(__float2half_rn(v1)) << 16);
                    *(uint32_t*)&Ch[(size_t)r0 * N + c0] = p;
                }
                if (r0 + 8 < M) {
                    uint32_t p = (uint32_t)__half_as_ushort(__float2half_rn(v2))
                               | ((uint32_t)__half_as_ushort(__float2half_rn(v3)) << 16);
                    *(uint32_t*)&Ch[(size_t)(r0 + 8) * N + c0] = p;
                }
            } else {
                if (r0 < M)     *(float2*)&Cm[(size_t)r0 * N + c0]       = make_float2(v0, v1);
                if (r0 + 8 < M) *(float2*)&Cm[(size_t)(r0 + 8) * N + c0] = make_float2(v2, v3);
            }
        }
    }
}

// ======================= fused temporal attention (MMA, L <= 16) =============
__global__ void __launch_bounds__(256)
attn_tmp_kernel(const h16* __restrict__ qkv, h16* __restrict__ outp, int L) {
    __shared__ __align__(16) char sm[8 * 3 * 2048];
    const int tid = threadIdx.x, lane = tid & 31, w = tid >> 5;
    const int g = blockIdx.x * 8 + w;
    const int s = g / NHEAD, h = g % NHEAD;
    uint32_t base = (uint32_t)__cvta_generic_to_shared(sm) + (uint32_t)w * 6144u;
    const h16* src0 = qkv + (size_t)s * L * 3 * CDIM + h * HDIM;

    for (int i = lane; i < 3 * 128; i += 32) {
        int p = i >> 7;
        int rem = i & 127;
        int tok = rem >> 3, c8 = rem & 7;
        uint4 v = make_uint4(0u, 0u, 0u, 0u);
        if (tok < L)
            v = *(const uint4*)(src0 + (size_t)tok * 3 * CDIM + p * CDIM + c8 * 8);
        *(uint4*)(sm + w * 6144 + p * 2048 + swiz128(tok * 128 + c8 * 16)) = v;
    }
    __syncwarp();

    const uint32_t Qb = base, Kb = base + 2048u, Vb = base + 4096u;
    const int lr = lane & 15, lc = (lane >> 4) * 8;
    const int c2 = (lane & 3) * 2;

    float sacc[2][4];
    #pragma unroll
    for (int n = 0; n < 2; n++)
        #pragma unroll
        for (int e = 0; e < 4; e++) sacc[n][e] = 0.f;
    #pragma unroll
    for (int kc = 0; kc < 4; kc++) {
        uint32_t qf[4], kf[4];
        LDSM4(qf, Qb + swiz128(lr * 128 + (lc + kc * 16) * 2));
        LDSM4(kf, Kb + swiz128(lr * 128 + (lc + kc * 16) * 2));
        MMA_F16(sacc[0], qf, kf[0], kf[2]);
        MMA_F16(sacc[1], qf, kf[1], kf[3]);
    }
    #pragma unroll
    for (int nt = 0; nt < 2; nt++) {
        int nb = nt * 8 + c2;
        sacc[nt][0] = (nb     < L) ? sacc[nt][0] * ATT_SCALE : -1e30f;
        sacc[nt][1] = (nb + 1 < L) ? sacc[nt][1] * ATT_SCALE : -1e30f;
        sacc[nt][2] = (nb     < L) ? sacc[nt][2] * ATT_SCALE : -1e30f;
        sacc[nt][3] = (nb + 1 < L) ? sacc[nt][3] * ATT_SCALE : -1e30f;
    }
    float bm0 = fmaxf(fmaxf(sacc[0][0], sacc[0][1]), fmaxf(sacc[1][0], sacc[1][1]));
    float bm1 = fmaxf(fmaxf(sacc[0][2], sacc[0][3]), fmaxf(sacc[1][2], sacc[1][3]));
    bm0 = fmaxf(bm0, __shfl_xor_sync(0xffffffffu, bm0, 1));
    bm0 = fmaxf(bm0, __shfl_xor_sync(0xffffffffu, bm0, 2));
    bm1 = fmaxf(bm1, __shfl_xor_sync(0xffffffffu, bm1, 1));
    bm1 = fmaxf(bm1, __shfl_xor_sync(0xffffffffu, bm1, 2));
    uint32_t af[4];
    float ps0 = 0.f, ps1 = 0.f;
    #pragma unroll
    for (int nt = 0; nt < 2; nt++) {
        h16 p0 = __float2half_rn(__expf(sacc[nt][0] - bm0));
        h16 p1 = __float2half_rn(__expf(sacc[nt][1] - bm0));
        h16 p2 = __float2half_rn(__expf(sacc[nt][2] - bm1));
        h16 p3 = __float2half_rn(__expf(sacc[nt][3] - bm1));
        af[nt * 2]     = (uint32_t)__half_as_ushort(p0) | ((uint32_t)__half_as_ushort(p1) << 16);
        af[nt * 2 + 1] = (uint32_t)__half_as_ushort(p2) | ((uint32_t)__half_as_ushort(p3) << 16);
        ps0 += __half2float(p0) + __half2float(p1);
        ps1 += __half2float(p2) + __half2float(p3);
    }
    ps0 += __shfl_xor_sync(0xffffffffu, ps0, 1);
    ps0 += __shfl_xor_sync(0xffffffffu, ps0, 2);
    ps1 += __shfl_xor_sync(0xffffffffu, ps1, 1);
    ps1 += __shfl_xor_sync(0xffffffffu, ps1, 2);

    float o[8][4];
    #pragma unroll
    for (int n = 0; n < 8; n++)
        #pragma unroll
        for (int e = 0; e < 4; e++) o[n][e] = 0.f;
    #pragma unroll
    for (int vd = 0; vd < 4; vd++) {
        uint32_t vf[4];
        LDSM4T(vf, Vb + swiz128(lr * 128 + (lc + vd * 16) * 2));
        MMA_F16(o[vd * 2],     af, vf[0], vf[1]);
        MMA_F16(o[vd * 2 + 1], af, vf[2], vf[3]);
    }

    float inv0 = 1.f / ps0, inv1 = 1.f / ps1;
    int q0 = lane >> 2, q1 = q0 + 8;
    #pragma unroll
    for (int n = 0; n < 8; n++) {
        int dim = n * 8 + c2;
        if (q0 < L) {
            uint32_t p = (uint32_t)__half_as_ushort(__float2half_rn(o[n][0] * inv0))
                       | ((uint32_t)__half_as_ushort(__float2half_rn(o[n][1] * inv0)) << 16);
            *(uint32_t*)&outp[((size_t)s * L + q0) * CDIM + h * HDIM + dim] = p;
        }
        if (q1 < L) {
            uint32_t p = (uint32_t)__half_as_ushort(__float2half_rn(o[n][2] * inv1))
                       | ((uint32_t)__half_as_ushort(__float2half_rn(o[n][3] * inv1)) << 16);
            *(uint32_t*)&outp[((size_t)s * L + q1) * CDIM + h * HDIM + dim] = p;
        }
    }
}

// ======================= fused spatial flash attention =======================
#define FLP 208
#define FNB 13
#define FQKV_BYTES 26624
#define FLASH_SMEM (3 * FQKV_BYTES)

__global__ void __launch_bounds__(256)
flash_sp_kernel(const h16* __restrict__ qkvh, h16* __restrict__ outp) {
    extern __shared__ __align__(16) char sm[];
    uint32_t sb = (uint32_t)__cvta_generic_to_shared(sm);
    const int bh = blockIdx.x;
    const int s = bh / NHEAD, h = bh % NHEAD;
    const int tid = threadIdx.x, lane = tid & 31, w = tid >> 5;

    for (int i = tid; i < 3 * FLP * 8; i += 256) {
        int p = i / (FLP * 8);
        int rem = i % (FLP * 8);
        int tok = rem >> 3, c8 = rem & 7;
        uint4 v = make_uint4(0u, 0u, 0u, 0u);
        if (tok < LSP) {
            const h16* src = qkvh + ((size_t)(s * LSP + tok)) * (3 * CDIM)
                           + p * CDIM + h * HDIM + c8 * 8;
            v = *(const uint4*)src;
        }
        *(uint4*)(sm + p * FQKV_BYTES + swiz128(tok * 128 + c8 * 16)) = v;
    }
    __syncthreads();
    const uint32_t Qb = sb, Kb = sb + FQKV_BYTES, Vb = sb + 2u * FQKV_BYTES;

    const int lr = lane & 15, lc = (lane >> 4) * 8;
    const int c2 = (lane & 3) * 2;

    for (int qt = w; qt < FNB; qt += 8) {
        uint32_t qf[4][4];
        #pragma unroll
        for (int kc = 0; kc < 4; kc++)
            LDSM4(qf[kc], Qb + swiz128((qt * 16 + lr) * 128 + (lc + kc * 16) * 2));

        float o[8][4];
        #pragma unroll
        for (int n = 0; n < 8; n++)
            #pragma unroll
            for (int e = 0; e < 4; e++) o[n][e] = 0.f;
        float m0 = -1e30f, m1 = -1e30f, l0 = 0.f, l1 = 0.f;

        for (int blk = 0; blk < FNB; blk++) {
            float sacc[2][4];
            #pragma unroll
            for (int n = 0; n < 2; n++)
                #pragma unroll
                for (int e = 0; e < 4; e++) sacc[n][e] = 0.f;
            #pragma unroll
            for (int kc = 0; kc < 4; kc++) {
                uint32_t kf[4];
                LDSM4(kf, Kb + swiz128((blk * 16 + lr) * 128 + (lc + kc * 16) * 2));
                MMA_F16(sacc[0], qf[kc], kf[0], kf[2]);
                MMA_F16(sacc[1], qf[kc], kf[1], kf[3]);
            }
            #pragma unroll
            for (int nt = 0; nt < 2; nt++) {
                int nb = blk * 16 + nt * 8 + c2;
                sacc[nt][0] = (nb     < LSP) ? sacc[nt][0] * ATT_SCALE : -1e30f;
                sacc[nt][1] = (nb + 1 < LSP) ? sacc[nt][1] * ATT_SCALE : -1e30f;
                sacc[nt][2] = (nb     < LSP) ? sacc[nt][2] * ATT_SCALE : -1e30f;
                sacc[nt][3] = (nb + 1 < LSP) ? sacc[nt][3] * ATT_SCALE : -1e30f;
            }
            float bm0 = fmaxf(fmaxf(sacc[0][0], sacc[0][1]), fmaxf(sacc[1][0], sacc[1][1]));
            float bm1 = fmaxf(fmaxf(sacc[0][2], sacc[0][3]), fmaxf(sacc[1][2], sacc[1][3]));
            bm0 = fmaxf(bm0, __shfl_xor_sync(0xffffffffu, bm0, 1));
            bm0 = fmaxf(bm0, __shfl_xor_sync(0xffffffffu, bm0, 2));
            bm1 = fmaxf(bm1, __shfl_xor_sync(0xffffffffu, bm1, 1));
            bm1 = fmaxf(bm1, __shfl_xor_sync(0xffffffffu, bm1, 2));
            float mn0 = fmaxf(m0, bm0), mn1 = fmaxf(m1, bm1);
            float a0 = __expf(m0 - mn0), a1 = __expf(m1 - mn1);
            m0 = mn0; m1 = mn1;
            l0 *= a0; l1 *= a1;
            #pragma unroll
            for (int n = 0; n < 8; n++) {
                o[n][0] *= a0; o[n][1] *= a0;
                o[n][2] *= a1; o[n][3] *= a1;
            }
            uint32_t af[4];
            float ps0 = 0.f, ps1 = 0.f;
            #pragma unroll
            for (int nt = 0; nt < 2; nt++) {
                h16 p0 = __float2half_rn(__expf(sacc[nt][0] - mn0));
                h16 p1 = __float2half_rn(__expf(sacc[nt][1] - mn0));
                h16 p2 = __float2half_rn(__expf(sacc[nt][2] - mn1));
                h16 p3 = __float2half_rn(__expf(sacc[nt][3] - mn1));
                af[nt * 2]     = (uint32_t)__half_as_ushort(p0)
                               | ((uint32_t)__half_as_ushort(p1) << 16);
                af[nt * 2 + 1] = (uint32_t)__half_as_ushort(p2)
                               | ((uint32_t)__half_as_ushort(p3) << 16);
                ps0 += __half2float(p0) + __half2float(p1);
                ps1 += __half2float(p2) + __half2float(p3);
            }
            ps0 += __shfl_xor_sync(0xffffffffu, ps0, 1);
            ps0 += __shfl_xor_sync(0xffffffffu, ps0, 2);
            ps1 += __shfl_xor_sync(0xffffffffu, ps1, 1);
            ps1 += __shfl_xor_sync(0xffffffffu, ps1, 2);
            l0 += ps0; l1 += ps1;
            #pragma unroll
            for (int vd = 0; vd < 4; vd++) {
                uint32_t vf[4];
                LDSM4T(vf, Vb + swiz128((blk * 16 + lr) * 128 + (lc + vd * 16) * 2));
                MMA_F16(o[vd * 2],     af, vf[0], vf[1]);
                MMA_F16(o[vd * 2 + 1], af, vf[2], vf[3]);
            }
        }
        float inv0 = 1.f / l0, inv1 = 1.f / l1;
        int q0 = qt * 16 + (lane >> 2), q1 = q0 + 8;
        #pragma unroll
        for (int n = 0; n < 8; n++) {
            int dim = n * 8 + c2;
            if (q0 < LSP) {
                uint32_t p = (uint32_t)__half_as_ushort(__float2half_rn(o[n][0] * inv0))
                           | ((uint32_t)__half_as_ushort(__float2half_rn(o[n][1] * inv0)) << 16);
                *(uint32_t*)&outp[((size_t)(s * LSP + q0)) * CDIM + h * HDIM + dim] = p;
            }
            if (q1 < LSP) {
                uint32_t p = (uint32_t)__half_as_ushort(__float2half_rn(o[n][2] * inv1))
                           | ((uint32_t)__half_as_ushort(__float2half_rn(o[n][3] * inv1)) << 16);
                *(uint32_t*)&outp[((size_t)(s * LSP + q1)) * CDIM + h * HDIM + dim] = p;
            }
        }
    }
}

// ------------------------- LayerNorm primitives -----------------------------
__device__ __forceinline__ float2 ln_stats_val(float s, float ss) {
    __shared__ float sm0[8], sm1[8];
    #pragma unroll
    for (int o = 16; o > 0; o >>= 1) {
        s  += __shfl_down_sync(0xffffffffu, s,  o);
        ss += __shfl_down_sync(0xffffffffu, ss, o);
    }
    int w = threadIdx.x >> 5;
    if ((threadIdx.x & 31) == 0) { sm0[w] = s; sm1[w] = ss; }
    __syncthreads();
    if (threadIdx.x == 0) {
        float a = 0.f, b2 = 0.f;
        int nw = blockDim.x >> 5;
        for (int i = 0; i < nw; i++) { a += sm0[i]; b2 += sm1[i]; }
        sm0[0] = a; sm1[0] = b2;
    }
    __syncthreads();
    float mean = sm0[0] * (1.f / CDIM);
    float var  = sm1[0] * (1.f / CDIM) - mean * mean;
    return make_float2(mean, rsqrtf(var + 1e-5f));
}

__device__ __forceinline__ float2 ln_stats(const float* __restrict__ src) {
    float s = 0.f, ss = 0.f;
    for (int c = threadIdx.x; c < CDIM; c += blockDim.x) {
        float v = src[c];
        s += v; ss += v * v;
    }
    return ln_stats_val(s, ss);
}

__device__ __forceinline__ void ln_row(const float* __restrict__ src,
                                       float* __restrict__ dst,
                                       const float* __restrict__ g,
                                       const float* __restrict__ bta) {
    float2 st = ln_stats(src);
    for (int c = threadIdx.x; c < CDIM; c += blockDim.x)
        dst[c] = (src[c] - st.x) * st.y * g[c] + bta[c];
}

__device__ __forceinline__ void ln_row_h(const float* __restrict__ src,
                                         h16* __restrict__ dh,
                                         const float* __restrict__ g,
                                         const float* __restrict__ bta) {
    float2 st = ln_stats(src);
    for (int c = threadIdx.x; c < CDIM; c += blockDim.x)
        dh[c] = __float2half_rn((src[c] - st.x) * st.y * g[c] + bta[c]);
}

__global__ void ln_xt_kernel(const float* __restrict__ x, h16* __restrict__ oh,
                             const float* __restrict__ g, const float* __restrict__ b) {
    int r = blockIdx.x;
    int bb = r / KT, off = r % KT;
    ln_row_h(x + ((size_t)bb * LSEQ + 1 + off) * CDIM, oh + (size_t)r * CDIM, g, b);
}

__global__ void ln_cls_kernel(const float* __restrict__ in, float* __restrict__ out,
                              const float* __restrict__ g, const float* __restrict__ b) {
    int r = blockIdx.x;
    ln_row(in + (size_t)r * LSP * CDIM, out + (size_t)r * CDIM, g, b);
}

__global__ void build_xs_ln_kernel(const float* __restrict__ x, const float* __restrict__ xtfull,
                                   const float* __restrict__ g, const float* __restrict__ bta,
                                   h16* __restrict__ oh) {
    int r = blockIdx.x;
    int s = r / LSP, i = r % LSP;
    int bb = s / TT, t = s % TT;
    const float* src = (i == 0)
        ? (x + (size_t)bb * LSEQ * CDIM)
        : (xtfull + ((size_t)bb * KT + (size_t)(i - 1) * TT + t) * CDIM);
    ln_row_h(src, oh + (size_t)r * CDIM, g, bta);
}

__global__ void build_xcat_ln_kernel(const float* __restrict__ x, const float* __restrict__ xtfull,
                                     const float* __restrict__ ressp, const float* __restrict__ clsout,
                                     const float* __restrict__ g, const float* __restrict__ bta,
                                     float* __restrict__ xcat, h16* __restrict__ oh) {
    int r = blockIdx.x;
    int bb = r / LSEQ, i = r % LSEQ;
    float v[3];
    float s = 0.f, ss = 0.f;
    #pragma unroll
    for (int e = 0; e < 3; e++) {
        int c = threadIdx.x + e * 256;
        float val;
        if (i == 0) {
            val = x[(size_t)bb * LSEQ * CDIM + c] + clsout[(size_t)bb * CDIM + c];
        } else {
            int n = i - 1;
            int k = n / TT, t = n % TT;
            val = xtfull[((size_t)bb * KT + n) * CDIM + c]
                + ressp[(((size_t)(bb * TT + t)) * LSP + 1 + k) * CDIM + c];
        }
        v[e] = val;
        xcat[(size_t)r * CDIM + c] = val;
        s += val; ss += val * val;
    }
    float2 st = ln_stats_val(s, ss);
    #pragma unroll
    for (int e = 0; e < 3; e++) {
        int c = threadIdx.x + e * 256;
        oh[(size_t)r * CDIM + c] = __float2half_rn((v[e] - st.x) * st.y * g[c] + bta[c]);
    }
}

// ------------------------- pointwise steps ----------------------------------
// blend fp16 inputs, fp16 output (for Wtfc A-plane)
__global__ void combine_kernel(const h16* __restrict__ x16, const h16* __restrict__ x8,
                               const h16* __restrict__ x4, h16* __restrict__ oh) {
    size_t idx = (size_t)blockIdx.x * blockDim.x + threadIdx.x;
    size_t tot = (size_t)MT * CDIM;
    if (idx >= tot) return;
    int c = (int)(idx % CDIM);
    size_t row = idx / CDIM;
    int j = (int)(row / TT), t = (int)(row % TT);
    float v = __half2float(x16[idx]);
    if (t >= 8) {
        float v8 = __half2float(x8[((size_t)j * 8 + (t - 8)) * CDIM + c]);
        if (t >= 12) v8 = 0.5f * v8 + 0.5f * __half2float(x4[((size_t)j * 4 + (t - 12)) * CDIM + c]);
        v = 0.5f * v + 0.5f * v8;
    }
    oh[idx] = __float2half_rn(v);
}

__global__ void cls_attn_kernel(const float* __restrict__ clssp, float* __restrict__ out) {
    int b = blockIdx.x;
    __shared__ float dots[TT];
    __shared__ float wts[TT];
    int w = threadIdx.x >> 5, lane = threadIdx.x & 31;
    const float* base = clssp + (size_t)b * TT * CDIM;
    const float* tgt = base + (size_t)(TT - 1) * CDIM;
    for (int t = w; t < TT; t += 8) {
        float sd = 0.f;
        for (int c = lane; c < CDIM; c += 32) sd = fmaf(tgt[c], base[(size_t)t * CDIM + c], sd);
        #pragma unroll
        for (int o = 16; o > 0; o >>= 1) sd += __shfl_xor_sync(0xffffffffu, sd, o);
        if (lane == 0) dots[t] = sd;
    }
    __syncthreads();
    if (threadIdx.x == 0) {
        float mx = -1e30f;
        for (int t = 0; t < TT; t++) mx = fmaxf(mx, dots[t]);
        float s = 0.f;
        for (int t = 0; t < TT; t++) { float e = expf(dots[t] - mx); wts[t] = e; s += e; }
        float inv = 1.f / s;
        for (int t = 0; t < TT; t++) wts[t] *= inv;
    }
    __syncthreads();
    for (int c = threadIdx.x; c < CDIM; c += blockDim.x) {
        float a = 0.f;
        #pragma unroll
        for (int t = 0; t < TT; t++) a = fmaf(wts[t], base[(size_t)t * CDIM + c], a);
        out[(size_t)b * CDIM + c] = a;
    }
}

// ------------------------- host orchestration -------------------------------
static inline void gemm5(const h16* Ah, const h16* Bh, const float* bias,
                         const float* resid, int rmode,
                         float* C, h16* Ch, int M, int N, int K, int act, int amap) {
    dim3 blk(256);
    dim3 grd(N / 128, (M + 127) / 128);
    gemm_tc_kernel<<<grd, blk, GEMM_SMEM>>>(Ah, Bh, bias, resid, rmode, C, Ch,
                                            M, N, K, act, amap);
}

extern "C" void kernel_launch(void* const* d_in, const int* in_sizes, int n_in,
                              void* d_out, int out_size) {
    const float* x       = (const float*)d_in[0];
    const float* ln1_g   = (const float*)d_in[4];
    const float* ln1_b   = (const float*)d_in[5];
    const float* lnt_g   = (const float*)d_in[6];
    const float* lnt_b   = (const float*)d_in[7];
    const float* ln2_g   = (const float*)d_in[8];
    const float* ln2_b   = (const float*)d_in[9];
    const float* lncls_g = (const float*)d_in[10];
    const float* lncls_b = (const float*)d_in[11];
    const float* Wqkv_s  = (const float*)d_in[12];
    const float* Wproj_s = (const float*)d_in[13];
    const float* bproj_s = (const float*)d_in[14];
    const float* Wqkv4   = (const float*)d_in[15];
    const float* Wqkv8   = (const float*)d_in[16];
    const float* Wqkv16  = (const float*)d_in[17];
    const float* Wp4     = (const float*)d_in[18];
    const float* bp4     = (const float*)d_in[19];
    const float* Wp8     = (const float*)d_in[20];
    const float* bp8     = (const float*)d_in[21];
    const float* Wp16    = (const float*)d_in[22];
    const float* bp16    = (const float*)d_in[23];
    const float* Wtfc    = (const float*)d_in[24];
    const float* btfc    = (const float*)d_in[25];
    const float* Wfc1    = (const float*)d_in[26];
    const float* bfc1    = (const float*)d_in[27];
    const float* Wfc2    = (const float*)d_in[28];
    const float* bfc2    = (const float*)d_in[29];
    float* out = (float*)d_out;

    cudaFuncSetAttribute(gemm_tc_kernel,
                         cudaFuncAttributeMaxDynamicSharedMemorySize, GEMM_SMEM);
    cudaFuncSetAttribute(flash_sp_kernel,
                         cudaFuncAttributeMaxDynamicSharedMemorySize, FLASH_SMEM);

    float *xtfull, *ressp, *clssp, *clsout, *xcat;
    h16 *pah, *pbh, *pch, *h1h, *wh, *qkvh, *x16h, *x8h, *x4h;
    cudaGetSymbolAddress((void**)&xtfull, g_xtfull);
    cudaGetSymbolAddress((void**)&ressp,  g_ressp);
    cudaGetSymbolAddress((void**)&clssp,  g_clssp);
    cudaGetSymbolAddress((void**)&clsout, g_clsout);
    cudaGetSymbolAddress((void**)&xcat,   g_xcat);
    cudaGetSymbolAddress((void**)&pah,    g_pah);
    cudaGetSymbolAddress((void**)&pbh,    g_pbh);
    cudaGetSymbolAddress((void**)&pch,    g_pch);
    cudaGetSymbolAddress((void**)&h1h,    g_h1h);
    cudaGetSymbolAddress((void**)&wh,     g_wh);
    cudaGetSymbolAddress((void**)&qkvh,   g_qkvh);
    cudaGetSymbolAddress((void**)&x16h,   g_x16h);
    cudaGetSymbolAddress((void**)&x8h,    g_x8h);
    cudaGetSymbolAddress((void**)&x4h,    g_x4h);

    // 0) weight fp16 conversion — single launch
    {
        WPack p;
        const float* srcs[11] = {Wqkv_s, Wqkv4, Wqkv8, Wqkv16, Wproj_s, Wp4,
                                 Wp8, Wp16, Wtfc, Wfc1, Wfc2};
        unsigned offs[11] = {OFF_QKV_S, OFF_QKV4, OFF_QKV8, OFF_QKV16, OFF_P_S,
                             OFF_P4, OFF_P8, OFF_P16, OFF_TFC, OFF_FC1, OFF_FC2};
        unsigned n4s[11] = {442368u, 442368u, 442368u, 442368u, 147456u,
                            147456u, 147456u, 147456u, 147456u, 589824u, 589824u};
        for (int i = 0; i < 11; i++) { p.src[i] = srcs[i]; p.dstoff[i] = offs[i]; p.n4[i] = n4s[i]; }
        convW_all_kernel<<<dim3(2304, 11), 256>>>(p, wh);
    }

    // 1) LN over temporal sequences -> fp16 plane
    ln_xt_kernel<<<MT, 256>>>(x, pah, lnt_g, lnt_b);

    #define RUN_TMHA(QKVOFF, POFF, BP, OUTH, L, AMAP) do {                       \
        int M_ = BKR * (L);                                                      \
        gemm5(pah, wh + (QKVOFF), nullptr, nullptr, 0, nullptr, qkvh,            \
              M_, 3 * CDIM, CDIM, 0, (AMAP));                                    \
        attn_tmp_kernel<<<(BKR * NHEAD) / 8, 256>>>(qkvh, pbh, (L));             \
        gemm5(pbh, wh + (POFF), (BP), nullptr, 0, nullptr, (OUTH),               \
              M_, CDIM, CDIM, 0, 0);                                             \
    } while (0)

    // 2) Temporal MHAs (gather folded into qkv GEMM A-map; fp16 proj outputs)
    RUN_TMHA(OFF_QKV16, OFF_P16, bp16, x16h, 16, 0);
    RUN_TMHA(OFF_QKV8,  OFF_P8,  bp8,  x8h,  8,  8);
    RUN_TMHA(OFF_QKV4,  OFF_P4,  bp4,  x4h,  4,  4);

    // 3) Blend scales (fp16 in/out)
    {
        size_t tot = (size_t)MT * CDIM;
        combine_kernel<<<(int)((tot + 255) / 256), 256>>>(x16h, x8h, x4h, pch);
    }

    // 4) xt_full = blend @ Wtfc + btfc + x residual (fused epilogue)
    gemm5(pch, wh + OFF_TFC, btfc, x, 2, xtfull, nullptr, MT, CDIM, CDIM, 0, 0);

    // 5) Spatial MHA: LN -> qkv(fp16) -> flash -> proj
    build_xs_ln_kernel<<<MSP, 256>>>(x, xtfull, ln1_g, ln1_b, pah);
    gemm5(pah, wh + OFF_QKV_S, nullptr, nullptr, 0, nullptr, qkvh,
          MSP, 3 * CDIM, CDIM, 0, 0);
    flash_sp_kernel<<<SSP * NHEAD, 256, FLASH_SMEM>>>(qkvh, pbh);
    gemm5(pbh, wh + OFF_P_S, bproj_s, nullptr, 0, ressp, nullptr,
          MSP, CDIM, CDIM, 0, 0);

    // 6) CLS path
    ln_cls_kernel<<<SSP, 256>>>(ressp, clssp, lncls_g, lncls_b);
    cls_attn_kernel<<<BBATCH, 256>>>(clssp, clsout);

    // 7) x_cat + LN2 fused
    build_xcat_ln_kernel<<<MOUT, 256>>>(x, xtfull, ressp, clsout, ln2_g, ln2_b, xcat, pah);

    // 8) MLP: fc1 (GELU, fp16 out) -> fc2 (+xcat residual, writes out)
    gemm5(pah, wh + OFF_FC1, bfc1, nullptr, 0, nullptr, h1h, MOUT, HID, CDIM, 1, 0);
    gemm5(h1h, wh + OFF_FC2, bfc2, xcat, 1, out, nullptr, MOUT, CDIM, HID, 0, 0);

    #undef RUN_TMHA
}